// round 11
// baseline (speedup 1.0000x reference)
#include <cuda_runtime.h>
#include <stdint.h>

// AE_spikes: ONE fused persistent kernel. Each CTA owns 8 batch rows and runs
// enc -> L1 -> repair -> L2 -> repair -> L3 -> repair -> L4 -> repair -> Out
// entirely from smem (masks never touch gmem). s8 mma.sync, 2 weight limbs
// base 254, exact int32 accumulation, fused fire-and-reset scan, in-CTA
// near-threshold flag + bit-exact fp32 repair (reference semantics).

#define BATCH  16384
#define TSTEPS 16
#define KP1    896
#define EPS    1e-3f
#define FCAPS  1024

// smem layout (bytes)
#define OFF_M0 0        // 8 x 896 u16, PERMUTED pairs          (14336)
#define OFF_A  14336    // A panel 128 x pitch144               (18432)
#define OFF_B  32768    // B: 2 x 18432 (L1); buf0 only for K128 (36864)
#define OFF_CS 51200    // scan buffer 128 x 68 f32 (overlays B1) (34816)
#define OFF_M1 86016    // 8 x 128 u16 unpermuted                (2048)
#define OFF_M2 88064
#define OFF_M3 90112
#define OFF_FC 92160    // flag counter (16B slot)
#define OFF_FL 92176    // flag list u32 x 1024                  (4096)
#define SMEMSZ 96272

// ---------------- weight scratch ----------------
__device__ int8_t g_Q1[2 * 128 * KP1];
__device__ int8_t g_Q2[2 * 128 * 128];
__device__ int8_t g_Q3[2 * 128 * 128];
__device__ int8_t g_Q4[2 * 784 * 128];
__device__ float  g_S1[128], g_S2[128], g_S3[128], g_S4[784];

// ---------------- helpers ----------------
__device__ __forceinline__ uint32_t smem_u32(const void* p) {
    uint32_t a;
    asm("{ .reg .u64 t; cvta.to.shared.u64 t, %1; cvt.u32.u64 %0, t; }"
        : "=r"(a) : "l"(p));
    return a;
}
__device__ __forceinline__ void mma8(int* d, const uint32_t* a, uint32_t b0, uint32_t b1) {
    asm volatile(
        "mma.sync.aligned.m16n8k32.row.col.s32.s8.s8.s32 "
        "{%0,%1,%2,%3}, {%4,%5,%6,%7}, {%8,%9}, {%0,%1,%2,%3};"
        : "+r"(d[0]), "+r"(d[1]), "+r"(d[2]), "+r"(d[3])
        : "r"(a[0]), "r"(a[1]), "r"(a[2]), "r"(a[3]), "r"(b0), "r"(b1));
}
__device__ __forceinline__ void cpa16(uint32_t dst, const void* src, uint32_t ssz) {
    asm volatile("cp.async.cg.shared.global [%0], [%1], 16, %2;"
                 :: "r"(dst), "l"(src), "r"(ssz));
}

// ---------------- weight split: all 4 sets in one launch ----------------
__device__ void wsplit_one(const float* W, int8_t* Q, float* S,
                           int N, int K, int KP, int j, int lane) {
    const float* w = W + (size_t)j * K;
    float m = 0.0f;
    for (int k = lane; k < K; k += 32) m = fmaxf(m, fabsf(w[k]));
#pragma unroll
    for (int o = 16; o; o >>= 1) m = fmaxf(m, __shfl_xor_sync(~0u, m, o));
    float s0 = (m > 0.0f) ? m / 127.0f : 1.0f;
    if (lane == 0) S[j] = s0;
    double s0d = (double)s0;
    for (int k = lane; k < KP; k += 32) {
        double q0 = 0.0, q1 = 0.0;
        if (k < K) {
            double wd = (double)w[k];
            q0 = fmin(fmax(rint(wd / s0d), -127.0), 127.0);
            double r1 = wd - q0 * s0d;
            q1 = fmin(fmax(rint(r1 * 254.0 / s0d), -127.0), 127.0);
        }
        size_t base = (size_t)j * KP + k, lstr = (size_t)N * KP;
        Q[base]        = (int8_t)(int)q0;
        Q[base + lstr] = (int8_t)(int)q1;
    }
}
__global__ void __launch_bounds__(32) wsplit_all(
    const float* __restrict__ W1, const float* __restrict__ W2,
    const float* __restrict__ W3, const float* __restrict__ W4)
{
    int bid = blockIdx.x, lane = threadIdx.x;
    if      (bid < 128) wsplit_one(W1, g_Q1, g_S1, 128, 784, KP1, bid, lane);
    else if (bid < 256) wsplit_one(W2, g_Q2, g_S2, 128, 128, 128, bid - 128, lane);
    else if (bid < 384) wsplit_one(W3, g_Q3, g_S3, 128, 128, 128, bid - 256, lane);
    else                wsplit_one(W4, g_Q4, g_S4, 784, 128, 128, bid - 384, lane);
}

// ---------------- device building blocks ----------------
// permuted-mask expansion (L1): lo=(m0,m2), hi=(m1,m3) per u64
__device__ __forceinline__ void expand_perm(const char* mskbase, char* abase,
                                            int kpu64, int p, int tid) {
    const uint64_t* m64 = (const uint64_t*)mskbase;
    int bl = tid >> 5, kq = tid & 31;
    uint64_t mv = m64[bl * kpu64 + p * 32 + kq];
    uint32_t lo = (uint32_t)mv;
    uint32_t hi = (uint32_t)(mv >> 32);
    char* arow = abase + (bl * 16) * 144 + kq * 4;
#pragma unroll
    for (int t = 0; t < 16; t++) {
        uint32_t a = (lo >> t) & 0x00010001u;
        uint32_t b = (hi >> t) & 0x00010001u;
        *(uint32_t*)(arow + t * 144) = a | (b << 8);
    }
}
// unpermuted-mask expansion (K=128 layers, runs once per layer)
__device__ __forceinline__ void expand_unperm(const uint16_t* msk, char* abase, int tid) {
    const uint64_t* m64 = (const uint64_t*)msk;
    int bl = tid >> 5, kq = tid & 31;
    uint64_t mv = m64[bl * 32 + kq];
    uint32_t lo = (uint32_t)mv, hi = (uint32_t)(mv >> 32);
    char* arow = abase + (bl * 16) * 144 + kq * 4;
#pragma unroll
    for (int t = 0; t < 16; t++) {
        uint32_t xl = (lo >> t) & 0x00010001u; xl |= xl >> 15;
        uint32_t xh = (hi >> t) & 0x00010001u; xh |= xh >> 15;
        uint32_t nib = (xl & 3u) | ((xh & 3u) << 2);
        *(uint32_t*)(arow + t * 144) = (nib * 0x00204081u) & 0x01010101u;
    }
}
__device__ __forceinline__ void mma_panel(const char* abase, const char* bbase,
                                          int wm2, int wn, int g, int tg,
                                          int (&D0)[2][4][4], int (&D1)[2][4][4]) {
#pragma unroll
    for (int ch = 0; ch < 4; ch++) {
        uint32_t afr[2][4];
#pragma unroll
        for (int mi = 0; mi < 2; mi++) {
            const char* ab = abase + (wm2 * 32 + mi * 16) * 144 + ch * 32;
            afr[mi][0] = *(const uint32_t*)(ab + g * 144 + tg * 4);
            afr[mi][1] = *(const uint32_t*)(ab + (g + 8) * 144 + tg * 4);
            afr[mi][2] = *(const uint32_t*)(ab + g * 144 + 16 + tg * 4);
            afr[mi][3] = *(const uint32_t*)(ab + (g + 8) * 144 + 16 + tg * 4);
        }
#pragma unroll
        for (int ni = 0; ni < 4; ni++) {
            const char* bb = bbase + (wn * 32 + ni * 8 + g) * 144 + ch * 32;
            uint32_t b00 = *(const uint32_t*)(bb + tg * 4);
            uint32_t b01 = *(const uint32_t*)(bb + 16 + tg * 4);
            uint32_t b10 = *(const uint32_t*)(bb + 9216 + tg * 4);
            uint32_t b11 = *(const uint32_t*)(bb + 9216 + 16 + tg * 4);
            mma8(D0[0][ni], afr[0], b00, b01);
            mma8(D0[1][ni], afr[1], b00, b01);
            mma8(D1[0][ni], afr[0], b10, b11);
            mma8(D1[1][ni], afr[1], b10, b11);
        }
    }
}

// shared repair scan: lanes 0-15 pair A, 16-31 pair B (acc per lane = per t)
__device__ __forceinline__ uint32_t repair_scan(float acc, float bj, int lane) {
    float v = 0.0f;
    uint32_t msk = 0;
#pragma unroll
    for (int t = 0; t < TSTEPS; t++) {
        float a = __shfl_sync(0xFFFFFFFFu, acc, (lane & 16) + t);
        v = (v + a) + bj;
        if (v >= 1.0f) { msk |= (1u << t); v -= 1.0f; }
    }
    return msk;
}

// ---------------- the fused kernel ----------------
template <int NT, int NOUT, bool IS_LAST>
__device__ void layer_k128(char* sm, uint32_t sbase, const uint16_t* msk_in,
                           const int8_t* Q, const float* S, const float* bias,
                           uint16_t* msk_out, float* Out, int b0,
                           int tid, int wm2, int wn, int g, int tg)
{
    expand_unperm(msk_in, sm + OFF_A, tid);
    auto loadB = [&](int nt) {
        const int n0 = nt * 64;
        for (int v = tid; v < 1024; v += 256) {
            int l = v >> 9, rem = v & 511, r = rem >> 3, c8 = rem & 7;
            int row = n0 + r;
            uint32_t ssz = (row < NOUT) ? 16u : 0u;
            int rc = row < NOUT ? row : 0;
            const int8_t* src = Q + ((size_t)l * NOUT + rc) * 128 + c8 * 16;
            cpa16(sbase + OFF_B + l * 9216 + r * 144 + c8 * 16, src, ssz);
        }
        asm volatile("cp.async.commit_group;");
    };
    loadB(0);
    asm volatile("cp.async.wait_group 0;");
    __syncthreads();                         // A + B(0) ready

#pragma unroll 1
    for (int nt = 0; nt < NT; nt++) {
        const int n0 = nt * 64;
        int D0[2][4][4], D1[2][4][4];
#pragma unroll
        for (int mi = 0; mi < 2; mi++)
#pragma unroll
            for (int ni = 0; ni < 4; ni++)
#pragma unroll
                for (int r = 0; r < 4; r++) { D0[mi][ni][r] = 0; D1[mi][ni][r] = 0; }

        mma_panel(sm + OFF_A, sm + OFF_B, wm2, wn, g, tg, D0, D1);
        __syncthreads();                     // B consumed by all warps
        if (nt + 1 < NT) loadB(nt + 1);      // overlap load w/ combine+scan

        float* cs = (float*)(sm + OFF_CS);
#pragma unroll
        for (int mi = 0; mi < 2; mi++)
#pragma unroll
            for (int ni = 0; ni < 4; ni++)
#pragma unroll
                for (int r = 0; r < 4; r++) {
                    int row = wm2 * 32 + mi * 16 + g + (r >> 1) * 8;
                    int col = wn * 32 + ni * 8 + tg * 2 + (r & 1);
                    int jg = n0 + col;
                    float s0 = __ldg(S + (jg < NOUT ? jg : 0));
                    cs[row * 68 + col] = s0 * (float)D0[mi][ni][r] +
                                         s0 * (1.0f / 254.0f) * (float)D1[mi][ni][r];
                }
        __syncthreads();                     // cs complete

#pragma unroll
        for (int u = 0; u < 2; u++) {
            int pr = tid + 256 * u;
            int j = pr & 63, bl = pr >> 6;
            int jj = n0 + j;
            if (jj < NOUT) {
                float bj = __ldg(bias + jj);
                const float* colp = cs + bl * 16 * 68 + j;
                float v = 0.0f;
                uint32_t msk = 0;
                bool flag = false;
#pragma unroll
                for (int t = 0; t < 16; t++) {
                    v = (v + colp[t * 68]) + bj;
                    flag |= (fabsf(v - 1.0f) < EPS);
                    if (v >= 1.0f) { msk |= (1u << t); v -= 1.0f; }
                }
                if (IS_LAST)
                    Out[(size_t)(b0 + bl) * NOUT + jj] = (float)__popc(msk) * 0.0625f;
                else
                    msk_out[bl * 128 + jj] = (uint16_t)msk;
                if (flag) {
                    int s = atomicAdd((int*)(sm + OFF_FC), 1);
                    if (s < FCAPS) ((uint32_t*)(sm + OFF_FL))[s] =
                        ((uint32_t)bl << 16) | (uint32_t)jj;
                }
            }
        }
        if (nt + 1 < NT) asm volatile("cp.async.wait_group 0;");
        __syncthreads();                     // scan done + next B ready
    }
}

template <bool IS_LAST>
__device__ void repair_k128(char* sm, const uint16_t* msk_prev, const float* W,
                            const float* bias, uint16_t* msk_fix, float* Out,
                            int NOUT, int b0, int tid, int lane, int wid)
{
    int n = *(int*)(sm + OFF_FC);
    if (n > FCAPS) n = FCAPS;
    for (int f0 = wid * 2; f0 < n; f0 += 16) {
        int s = f0 + (lane >> 4), tl = lane & 15;
        float acc = 0.0f;
        int bl = 0, j = 0;
        bool act = (s < n);
        if (act) {
            uint32_t pk = ((uint32_t*)(sm + OFF_FL))[s];
            bl = (int)(pk >> 16); j = (int)(pk & 0xFFFFu);
            const float* wr = W + (size_t)j * 128;
            const uint32_t bit = 1u << tl;
            for (int i = 0; i < 128; i++)
                if (msk_prev[bl * 128 + i] & bit) acc += wr[i];
        }
        float bj = act ? __ldg(bias + j) : 0.0f;
        uint32_t msk = repair_scan(acc, bj, lane);
        if (act && (lane & 15) == 0) {
            if (IS_LAST)
                Out[(size_t)(b0 + bl) * NOUT + j] = (float)__popc(msk) * 0.0625f;
            else
                msk_fix[bl * 128 + j] = (uint16_t)msk;
        }
    }
    __syncthreads();
    if (tid == 0) *(int*)(sm + OFF_FC) = 0;
    __syncthreads();
}

__global__ void __launch_bounds__(256, 2) fused_spike(
    const float* __restrict__ F,
    const float* __restrict__ W1, const float* __restrict__ b1,
    const float* __restrict__ W2, const float* __restrict__ b2,
    const float* __restrict__ W3, const float* __restrict__ b3,
    const float* __restrict__ W4, const float* __restrict__ b4,
    float* __restrict__ Out)
{
    extern __shared__ __align__(16) char sm[];
    const uint32_t sbase = smem_u32(sm);
    const int tid = threadIdx.x;
    const int lane = tid & 31, wid = tid >> 5;
    const int wm2 = wid >> 1, wn = wid & 1;
    const int g = lane >> 2, tg = lane & 3;
    const int b0 = blockIdx.x * 8;

    // ---- encoder: bit-exact scans -> raw masks in A temp ----
    {
        uint16_t* raw = (uint16_t*)(sm + OFF_A);
        for (int u = tid; u < 8 * KP1; u += 256) {
            int bl = u / KP1, i = u - bl * KP1;
            unsigned m = 0;
            if (i < 784) {
                float x = F[(size_t)(b0 + bl) * 784 + i], v = 0.0f;
#pragma unroll
                for (int t = 0; t < TSTEPS; t++) {
                    v += x;
                    if (v >= 1.0f) { m |= (1u << t); v -= 1.0f; }
                }
            }
            raw[u] = (uint16_t)m;
        }
        if (tid == 0) *(int*)(sm + OFF_FC) = 0;
        __syncthreads();
        // permute into M0: (m0,m2)|(m1,m3) per u64
        const uint4* s = (const uint4*)(sm + OFF_A);
        uint4* d = (uint4*)(sm + OFF_M0);
        for (int u = tid; u < 8 * KP1 / 8; u += 256) {
            uint4 v = s[u], o;
            o.x = __byte_perm(v.x, v.y, 0x5410);
            o.y = __byte_perm(v.x, v.y, 0x7632);
            o.z = __byte_perm(v.z, v.w, 0x5410);
            o.w = __byte_perm(v.z, v.w, 0x7632);
            d[u] = o;
        }
        __syncthreads();
    }

    // ---- layer 1: K=896, 2 N-tiles, double-buffered K panels ----
    for (int nt = 0; nt < 2; nt++) {
        const int n0 = nt * 64;
        int D0[2][4][4], D1[2][4][4];
#pragma unroll
        for (int mi = 0; mi < 2; mi++)
#pragma unroll
            for (int ni = 0; ni < 4; ni++)
#pragma unroll
                for (int r = 0; r < 4; r++) { D0[mi][ni][r] = 0; D1[mi][ni][r] = 0; }

        auto loadB1 = [&](int p, int buf) {
            for (int v = tid; v < 1024; v += 256) {
                int l = v >> 9, rem = v & 511, r = rem >> 3, c8 = rem & 7;
                const int8_t* src = g_Q1 + ((size_t)l * 128 + n0 + r) * KP1 + p * 128 + c8 * 16;
                cpa16(sbase + OFF_B + buf * 18432 + l * 9216 + r * 144 + c8 * 16, src, 16u);
            }
            asm volatile("cp.async.commit_group;");
        };
        loadB1(0, 0);
#pragma unroll 1
        for (int p = 0; p < 7; p++) {
            const int buf = p & 1;
            if (p < 6) loadB1(p + 1, buf ^ 1);
            expand_perm(sm + OFF_M0, sm + OFF_A, KP1 / 4, p, tid);
            if (p < 6) asm volatile("cp.async.wait_group 1;");
            else       asm volatile("cp.async.wait_group 0;");
            __syncthreads();
            mma_panel(sm + OFF_A, sm + OFF_B + buf * 18432, wm2, wn, g, tg, D0, D1);
            __syncthreads();
        }
        float* cs = (float*)(sm + OFF_CS);
#pragma unroll
        for (int mi = 0; mi < 2; mi++)
#pragma unroll
            for (int ni = 0; ni < 4; ni++)
#pragma unroll
                for (int r = 0; r < 4; r++) {
                    int row = wm2 * 32 + mi * 16 + g + (r >> 1) * 8;
                    int col = wn * 32 + ni * 8 + tg * 2 + (r & 1);
                    float s0 = __ldg(g_S1 + n0 + col);
                    cs[row * 68 + col] = s0 * (float)D0[mi][ni][r] +
                                         s0 * (1.0f / 254.0f) * (float)D1[mi][ni][r];
                }
        __syncthreads();
#pragma unroll
        for (int u = 0; u < 2; u++) {
            int pr = tid + 256 * u;
            int j = pr & 63, bl = pr >> 6;
            int jj = n0 + j;
            float bj = __ldg(b1 + jj);
            const float* colp = cs + bl * 16 * 68 + j;
            float v = 0.0f;
            uint32_t msk = 0;
            bool flag = false;
#pragma unroll
            for (int t = 0; t < 16; t++) {
                v = (v + colp[t * 68]) + bj;
                flag |= (fabsf(v - 1.0f) < EPS);
                if (v >= 1.0f) { msk |= (1u << t); v -= 1.0f; }
            }
            ((uint16_t*)(sm + OFF_M1))[bl * 128 + jj] = (uint16_t)msk;
            if (flag) {
                int s = atomicAdd((int*)(sm + OFF_FC), 1);
                if (s < FCAPS) ((uint32_t*)(sm + OFF_FL))[s] =
                    ((uint32_t)bl << 16) | (uint32_t)jj;
            }
        }
        __syncthreads();
    }
    // ---- layer 1 repair (permuted M0 lookup, K=784, gmem W1) ----
    {
        int n = *(int*)(sm + OFF_FC);
        if (n > FCAPS) n = FCAPS;
        const uint64_t* m64 = (const uint64_t*)(sm + OFF_M0);
        for (int f0 = wid * 2; f0 < n; f0 += 16) {
            int s = f0 + (lane >> 4), tl = lane & 15;
            float acc = 0.0f;
            int bl = 0, j = 0;
            bool act = (s < n);
            if (act) {
                uint32_t pk = ((uint32_t*)(sm + OFF_FL))[s];
                bl = (int)(pk >> 16); j = (int)(pk & 0xFFFFu);
                const float* wr = W1 + (size_t)j * 784;
                const uint32_t bit = 1u << tl;
                for (int i = 0; i < 784; i++) {
                    uint64_t mv = m64[bl * 224 + (i >> 2)];
                    uint32_t half = (i & 1) ? (uint32_t)(mv >> 32) : (uint32_t)mv;
                    uint32_t mk = (half >> (((i >> 1) & 1) << 4)) & 0xFFFFu;
                    if (mk & bit) acc += wr[i];
                }
            }
            float bj = act ? __ldg(b1 + j) : 0.0f;
            uint32_t msk = repair_scan(acc, bj, lane);
            if (act && (lane & 15) == 0)
                ((uint16_t*)(sm + OFF_M1))[bl * 128 + j] = (uint16_t)msk;
        }
        __syncthreads();
        if (tid == 0) *(int*)(sm + OFF_FC) = 0;
        __syncthreads();
    }

    // ---- layers 2,3 (K=128, NOUT=128, 2 tiles) + repairs ----
    layer_k128<2, 128, false>(sm, sbase, (const uint16_t*)(sm + OFF_M1),
                              g_Q2, g_S2, b2, (uint16_t*)(sm + OFF_M2),
                              nullptr, b0, tid, wm2, wn, g, tg);
    repair_k128<false>(sm, (const uint16_t*)(sm + OFF_M1), W2, b2,
                       (uint16_t*)(sm + OFF_M2), nullptr, 128, b0, tid, lane, wid);

    layer_k128<2, 128, false>(sm, sbase, (const uint16_t*)(sm + OFF_M2),
                              g_Q3, g_S3, b3, (uint16_t*)(sm + OFF_M3),
                              nullptr, b0, tid, wm2, wn, g, tg);
    repair_k128<false>(sm, (const uint16_t*)(sm + OFF_M2), W3, b3,
                       (uint16_t*)(sm + OFF_M3), nullptr, 128, b0, tid, lane, wid);

    // ---- layer 4 (K=128, NOUT=784, 13 tiles) + repair ----
    layer_k128<13, 784, true>(sm, sbase, (const uint16_t*)(sm + OFF_M3),
                              g_Q4, g_S4, b4, nullptr, Out, b0,
                              tid, wm2, wn, g, tg);
    repair_k128<true>(sm, (const uint16_t*)(sm + OFF_M3), W4, b4,
                      nullptr, Out, 784, b0, tid, lane, wid);
}

// ---------------------------------------------------------------------------
extern "C" void kernel_launch(void* const* d_in, const int* in_sizes, int n_in,
                              void* d_out, int out_size)
{
    const float* features = (const float*)d_in[0];
    const float* W1 = (const float*)d_in[1];
    const float* b1 = (const float*)d_in[2];
    const float* W2 = (const float*)d_in[3];
    const float* b2 = (const float*)d_in[4];
    const float* W3 = (const float*)d_in[5];
    const float* b3 = (const float*)d_in[6];
    const float* W4 = (const float*)d_in[7];
    const float* b4 = (const float*)d_in[8];
    float* out = (float*)d_out;

    static bool attr_set = false;
    cudaFuncSetAttribute(fused_spike,
                         cudaFuncAttributeMaxDynamicSharedMemorySize, SMEMSZ);
    (void)attr_set;

    wsplit_all<<<1168, 32>>>(W1, W2, W3, W4);
    fused_spike<<<BATCH / 8, 256, SMEMSZ>>>(features, W1, b1, W2, b2,
                                            W3, b3, W4, b4, out);
}

// round 12
// speedup vs baseline: 1.0042x; 1.0042x over previous
#include <cuda_runtime.h>
#include <stdint.h>

// AE_spikes: ONE fused kernel, 8 batch rows per CTA, enc->L1->..->L4 all in
// smem. s8 mma.sync, 2 weight limbs base 254, exact int32 accumulation,
// fused fire-and-reset scan, in-CTA flag + bit-exact fp32 repair.
// R11: 3 CTAs/SM (smem 75.8KB via 2-pass scan buffer overlaid on consumed B
// buf + M3/M1 aliasing; reg cap 85 via launch_bounds(256,3) + E-trick
// combine E=254*D0+D1 -> one I2F).

#define BATCH  16384
#define TSTEPS 16
#define KP1    896
#define EPS    1e-3f
#define FCAPS  512

// smem layout (bytes)
#define OFF_M0 0        // 8 x 896 u16 PERMUTED                (14336)
#define OFF_A  14336    // A panel 128 x pitch144              (18432)
#define OFF_B  32768    // 2 x 18432 B bufs; CS overlays consumed buf
#define OFF_M1 69632    // 8 x 128 u16 (also reused as M3)      (2048)
#define OFF_M2 71680    //                                      (2048)
#define OFF_FC 73728    // flag counter                           (16)
#define OFF_FL 73744    // flag list u32 x 512                  (2048)
#define SMEMSZ 75792

// ---------------- weight scratch ----------------
__device__ int8_t g_Q1[2 * 128 * KP1];
__device__ int8_t g_Q2[2 * 128 * 128];
__device__ int8_t g_Q3[2 * 128 * 128];
__device__ int8_t g_Q4[2 * 784 * 128];
__device__ float  g_S1[128], g_S2[128], g_S3[128], g_S4[784];

// ---------------- helpers ----------------
__device__ __forceinline__ uint32_t smem_u32(const void* p) {
    uint32_t a;
    asm("{ .reg .u64 t; cvta.to.shared.u64 t, %1; cvt.u32.u64 %0, t; }"
        : "=r"(a) : "l"(p));
    return a;
}
__device__ __forceinline__ void mma8(int* d, const uint32_t* a, uint32_t b0, uint32_t b1) {
    asm volatile(
        "mma.sync.aligned.m16n8k32.row.col.s32.s8.s8.s32 "
        "{%0,%1,%2,%3}, {%4,%5,%6,%7}, {%8,%9}, {%0,%1,%2,%3};"
        : "+r"(d[0]), "+r"(d[1]), "+r"(d[2]), "+r"(d[3])
        : "r"(a[0]), "r"(a[1]), "r"(a[2]), "r"(a[3]), "r"(b0), "r"(b1));
}
__device__ __forceinline__ void cpa16(uint32_t dst, const void* src, uint32_t ssz) {
    asm volatile("cp.async.cg.shared.global [%0], [%1], 16, %2;"
                 :: "r"(dst), "l"(src), "r"(ssz));
}

// ---------------- weight split (one launch) ----------------
__device__ void wsplit_one(const float* W, int8_t* Q, float* S,
                           int N, int K, int KP, int j, int lane) {
    const float* w = W + (size_t)j * K;
    float m = 0.0f;
    for (int k = lane; k < K; k += 32) m = fmaxf(m, fabsf(w[k]));
#pragma unroll
    for (int o = 16; o; o >>= 1) m = fmaxf(m, __shfl_xor_sync(~0u, m, o));
    float s0 = (m > 0.0f) ? m / 127.0f : 1.0f;
    if (lane == 0) S[j] = s0;
    double s0d = (double)s0;
    for (int k = lane; k < KP; k += 32) {
        double q0 = 0.0, q1 = 0.0;
        if (k < K) {
            double wd = (double)w[k];
            q0 = fmin(fmax(rint(wd / s0d), -127.0), 127.0);
            double r1 = wd - q0 * s0d;
            q1 = fmin(fmax(rint(r1 * 254.0 / s0d), -127.0), 127.0);
        }
        size_t base = (size_t)j * KP + k, lstr = (size_t)N * KP;
        Q[base]        = (int8_t)(int)q0;
        Q[base + lstr] = (int8_t)(int)q1;
    }
}
__global__ void __launch_bounds__(32) wsplit_all(
    const float* __restrict__ W1, const float* __restrict__ W2,
    const float* __restrict__ W3, const float* __restrict__ W4)
{
    int bid = blockIdx.x, lane = threadIdx.x;
    if      (bid < 128) wsplit_one(W1, g_Q1, g_S1, 128, 784, KP1, bid, lane);
    else if (bid < 256) wsplit_one(W2, g_Q2, g_S2, 128, 128, 128, bid - 128, lane);
    else if (bid < 384) wsplit_one(W3, g_Q3, g_S3, 128, 128, 128, bid - 256, lane);
    else                wsplit_one(W4, g_Q4, g_S4, 784, 128, 128, bid - 384, lane);
}

// ---------------- device building blocks ----------------
__device__ __forceinline__ void expand_perm(const char* mskbase, char* abase,
                                            int kpu64, int p, int tid) {
    const uint64_t* m64 = (const uint64_t*)mskbase;
    int bl = tid >> 5, kq = tid & 31;
    uint64_t mv = m64[bl * kpu64 + p * 32 + kq];
    uint32_t lo = (uint32_t)mv;
    uint32_t hi = (uint32_t)(mv >> 32);
    char* arow = abase + (bl * 16) * 144 + kq * 4;
#pragma unroll
    for (int t = 0; t < 16; t++) {
        uint32_t a = (lo >> t) & 0x00010001u;
        uint32_t b = (hi >> t) & 0x00010001u;
        *(uint32_t*)(arow + t * 144) = a | (b << 8);
    }
}
__device__ __forceinline__ void expand_unperm(const uint16_t* msk, char* abase, int tid) {
    const uint64_t* m64 = (const uint64_t*)msk;
    int bl = tid >> 5, kq = tid & 31;
    uint64_t mv = m64[bl * 32 + kq];
    uint32_t lo = (uint32_t)mv, hi = (uint32_t)(mv >> 32);
    char* arow = abase + (bl * 16) * 144 + kq * 4;
#pragma unroll
    for (int t = 0; t < 16; t++) {
        uint32_t xl = (lo >> t) & 0x00010001u; xl |= xl >> 15;
        uint32_t xh = (hi >> t) & 0x00010001u; xh |= xh >> 15;
        uint32_t nib = (xl & 3u) | ((xh & 3u) << 2);
        *(uint32_t*)(arow + t * 144) = (nib * 0x00204081u) & 0x01010101u;
    }
}
__device__ __forceinline__ void mma_panel(const char* abase, const char* bbase,
                                          int wm2, int wn, int g, int tg,
                                          int (&D0)[2][4][4], int (&D1)[2][4][4]) {
#pragma unroll
    for (int ch = 0; ch < 4; ch++) {
        uint32_t afr[2][4];
#pragma unroll
        for (int mi = 0; mi < 2; mi++) {
            const char* ab = abase + (wm2 * 32 + mi * 16) * 144 + ch * 32;
            afr[mi][0] = *(const uint32_t*)(ab + g * 144 + tg * 4);
            afr[mi][1] = *(const uint32_t*)(ab + (g + 8) * 144 + tg * 4);
            afr[mi][2] = *(const uint32_t*)(ab + g * 144 + 16 + tg * 4);
            afr[mi][3] = *(const uint32_t*)(ab + (g + 8) * 144 + 16 + tg * 4);
        }
#pragma unroll
        for (int ni = 0; ni < 4; ni++) {
            const char* bb = bbase + (wn * 32 + ni * 8 + g) * 144 + ch * 32;
            uint32_t b00 = *(const uint32_t*)(bb + tg * 4);
            uint32_t b01 = *(const uint32_t*)(bb + 16 + tg * 4);
            mma8(D0[0][ni], afr[0], b00, b01);
            mma8(D0[1][ni], afr[1], b00, b01);
            uint32_t b10 = *(const uint32_t*)(bb + 9216 + tg * 4);
            uint32_t b11 = *(const uint32_t*)(bb + 9216 + 16 + tg * 4);
            mma8(D1[0][ni], afr[0], b10, b11);
            mma8(D1[1][ni], afr[1], b10, b11);
        }
    }
}

// combine (pass = which 64-row half): E = 254*D0 + D1, cs = (s0/254)*float(E)
__device__ __forceinline__ void combine_pass(
    float* cs, const float* S, int NOUT, int n0, int pass,
    int wm2, int wn, int g, int tg, int (&D0)[2][4][4], int (&D1)[2][4][4])
{
    if ((wm2 >> 1) != pass) return;
    int wl = wm2 & 1;
#pragma unroll
    for (int mi = 0; mi < 2; mi++)
#pragma unroll
        for (int ni = 0; ni < 4; ni++)
#pragma unroll
            for (int r = 0; r < 4; r++) {
                int row = wl * 32 + mi * 16 + g + (r >> 1) * 8;     // 0..63
                int col = wn * 32 + ni * 8 + tg * 2 + (r & 1);
                int jg = n0 + col;
                float sc = __ldg(S + (jg < NOUT ? jg : 0)) * (1.0f / 254.0f);
                int E = D0[mi][ni][r] * 254 + D1[mi][ni][r];
                cs[row * 68 + col] = sc * (float)E;
            }
}

// scan one 64-row half: 256 pairs, 1 per thread
template <bool IS_LAST>
__device__ __forceinline__ void scan_pass(
    char* sm, const float* cs, const float* bias, int NOUT, int n0, int pass,
    int tid, uint16_t* msk_out, float* Out, int b0)
{
    int j = tid & 63, bll = tid >> 6;
    int jj = n0 + j;
    if (jj < NOUT) {
        float bj = __ldg(bias + jj);
        const float* colp = cs + bll * 16 * 68 + j;
        float v = 0.0f;
        uint32_t msk = 0;
        bool flag = false;
#pragma unroll
        for (int t = 0; t < 16; t++) {
            v = (v + colp[t * 68]) + bj;
            flag |= (fabsf(v - 1.0f) < EPS);
            if (v >= 1.0f) { msk |= (1u << t); v -= 1.0f; }
        }
        int bl = pass * 4 + bll;
        if (IS_LAST)
            Out[(size_t)(b0 + bl) * NOUT + jj] = (float)__popc(msk) * 0.0625f;
        else
            msk_out[bl * 128 + jj] = (uint16_t)msk;
        if (flag) {
            int s = atomicAdd((int*)(sm + OFF_FC), 1);
            if (s < FCAPS) ((uint32_t*)(sm + OFF_FL))[s] =
                ((uint32_t)bl << 16) | (uint32_t)jj;
        }
    }
}

__device__ __forceinline__ uint32_t repair_scan(float acc, float bj, int lane) {
    float v = 0.0f;
    uint32_t msk = 0;
#pragma unroll
    for (int t = 0; t < TSTEPS; t++) {
        float a = __shfl_sync(0xFFFFFFFFu, acc, (lane & 16) + t);
        v = (v + a) + bj;
        if (v >= 1.0f) { msk |= (1u << t); v -= 1.0f; }
    }
    return msk;
}

// ---------------- K=128 layer (NT tiles in-CTA, 2-pass epilogue) ----------
template <int NT, int NOUT, bool IS_LAST>
__device__ void layer_k128(char* sm, uint32_t sbase, const uint16_t* msk_in,
                           const int8_t* Q, const float* S, const float* bias,
                           uint16_t* msk_out, float* Out, int b0,
                           int tid, int wm2, int wn, int g, int tg)
{
    expand_unperm(msk_in, sm + OFF_A, tid);
    auto loadB = [&](int nt) {
        const int n0 = nt * 64, buf = nt & 1;
        for (int v = tid; v < 1024; v += 256) {
            int l = v >> 9, rem = v & 511, r = rem >> 3, c8 = rem & 7;
            int row = n0 + r;
            uint32_t ssz = (row < NOUT) ? 16u : 0u;
            int rc = row < NOUT ? row : 0;
            cpa16(sbase + OFF_B + buf * 18432 + l * 9216 + r * 144 + c8 * 16,
                  Q + ((size_t)l * NOUT + rc) * 128 + c8 * 16, ssz);
        }
        asm volatile("cp.async.commit_group;");
    };
    loadB(0);
    asm volatile("cp.async.wait_group 0;");
    __syncthreads();                         // A + B(0) ready

#pragma unroll 1
    for (int nt = 0; nt < NT; nt++) {
        const int n0 = nt * 64, buf = nt & 1;
        int D0[2][4][4], D1[2][4][4];
#pragma unroll
        for (int mi = 0; mi < 2; mi++)
#pragma unroll
            for (int ni = 0; ni < 4; ni++)
#pragma unroll
                for (int r = 0; r < 4; r++) { D0[mi][ni][r] = 0; D1[mi][ni][r] = 0; }

        mma_panel(sm + OFF_A, sm + OFF_B + buf * 18432, wm2, wn, g, tg, D0, D1);
        __syncthreads();                     // B(buf) consumed
        if (nt + 1 < NT) loadB(nt + 1);      // into buf^1, overlaps epilogue

        float* cs = (float*)(sm + OFF_B + buf * 18432);   // overlay consumed buf
#pragma unroll
        for (int pass = 0; pass < 2; pass++) {
            combine_pass(cs, S, NOUT, n0, pass, wm2, wn, g, tg, D0, D1);
            __syncthreads();
            scan_pass<IS_LAST>(sm, cs, bias, NOUT, n0, pass, tid, msk_out, Out, b0);
            __syncthreads();
        }
        if (nt + 1 < NT) asm volatile("cp.async.wait_group 0;");
        __syncthreads();
    }
}

template <bool IS_LAST>
__device__ void repair_k128(char* sm, const uint16_t* msk_prev, const float* W,
                            const float* bias, uint16_t* msk_fix, float* Out,
                            int NOUT, int b0, int tid, int lane, int wid)
{
    int n = *(int*)(sm + OFF_FC);
    if (n > FCAPS) n = FCAPS;
    for (int f0 = wid * 2; f0 < n; f0 += 16) {
        int s = f0 + (lane >> 4), tl = lane & 15;
        float acc = 0.0f;
        int bl = 0, j = 0;
        bool act = (s < n);
        if (act) {
            uint32_t pk = ((uint32_t*)(sm + OFF_FL))[s];
            bl = (int)(pk >> 16); j = (int)(pk & 0xFFFFu);
            const float* wr = W + (size_t)j * 128;
            const uint32_t bit = 1u << tl;
            for (int i = 0; i < 128; i++)
                if (msk_prev[bl * 128 + i] & bit) acc += wr[i];
        }
        float bj = act ? __ldg(bias + j) : 0.0f;
        uint32_t msk = repair_scan(acc, bj, lane);
        if (act && (lane & 15) == 0) {
            if (IS_LAST)
                Out[(size_t)(b0 + bl) * NOUT + j] = (float)__popc(msk) * 0.0625f;
            else
                msk_fix[bl * 128 + j] = (uint16_t)msk;
        }
    }
    __syncthreads();
    if (tid == 0) *(int*)(sm + OFF_FC) = 0;
    __syncthreads();
}

// ---------------- the fused kernel ----------------
__global__ void __launch_bounds__(256, 3) fused_spike(
    const float* __restrict__ F,
    const float* __restrict__ W1, const float* __restrict__ b1,
    const float* __restrict__ W2, const float* __restrict__ b2,
    const float* __restrict__ W3, const float* __restrict__ b3,
    const float* __restrict__ W4, const float* __restrict__ b4,
    float* __restrict__ Out)
{
    extern __shared__ __align__(16) char sm[];
    const uint32_t sbase = smem_u32(sm);
    const int tid = threadIdx.x;
    const int lane = tid & 31, wid = tid >> 5;
    const int wm2 = wid >> 1, wn = wid & 1;
    const int g = lane >> 2, tg = lane & 3;
    const int b0 = blockIdx.x * 8;

    // ---- encoder (bit-exact) -> permuted M0 ----
    {
        uint16_t* raw = (uint16_t*)(sm + OFF_A);
        for (int u = tid; u < 8 * KP1; u += 256) {
            int bl = u / KP1, i = u - bl * KP1;
            unsigned m = 0;
            if (i < 784) {
                float x = F[(size_t)(b0 + bl) * 784 + i], v = 0.0f;
#pragma unroll
                for (int t = 0; t < TSTEPS; t++) {
                    v += x;
                    if (v >= 1.0f) { m |= (1u << t); v -= 1.0f; }
                }
            }
            raw[u] = (uint16_t)m;
        }
        if (tid == 0) *(int*)(sm + OFF_FC) = 0;
        __syncthreads();
        const uint4* s = (const uint4*)(sm + OFF_A);
        uint4* d = (uint4*)(sm + OFF_M0);
        for (int u = tid; u < 8 * KP1 / 8; u += 256) {
            uint4 v = s[u], o;
            o.x = __byte_perm(v.x, v.y, 0x5410);
            o.y = __byte_perm(v.x, v.y, 0x7632);
            o.z = __byte_perm(v.z, v.w, 0x5410);
            o.w = __byte_perm(v.z, v.w, 0x7632);
            d[u] = o;
        }
        __syncthreads();
    }

    // ---- layer 1: K=896, 2 N-tiles, double-buffered panels ----
    for (int nt = 0; nt < 2; nt++) {
        const int n0 = nt * 64;
        int D0[2][4][4], D1[2][4][4];
#pragma unroll
        for (int mi = 0; mi < 2; mi++)
#pragma unroll
            for (int ni = 0; ni < 4; ni++)
#pragma unroll
                for (int r = 0; r < 4; r++) { D0[mi][ni][r] = 0; D1[mi][ni][r] = 0; }

        auto loadB1 = [&](int p, int buf) {
            for (int v = tid; v < 1024; v += 256) {
                int l = v >> 9, rem = v & 511, r = rem >> 3, c8 = rem & 7;
                cpa16(sbase + OFF_B + buf * 18432 + l * 9216 + r * 144 + c8 * 16,
                      g_Q1 + ((size_t)l * 128 + n0 + r) * KP1 + p * 128 + c8 * 16, 16u);
            }
            asm volatile("cp.async.commit_group;");
        };
        loadB1(0, 0);
#pragma unroll 1
        for (int p = 0; p < 7; p++) {
            const int buf = p & 1;
            if (p < 6) loadB1(p + 1, buf ^ 1);
            expand_perm(sm + OFF_M0, sm + OFF_A, KP1 / 4, p, tid);
            if (p < 6) asm volatile("cp.async.wait_group 1;");
            else       asm volatile("cp.async.wait_group 0;");
            __syncthreads();
            mma_panel(sm + OFF_A, sm + OFF_B + buf * 18432, wm2, wn, g, tg, D0, D1);
            __syncthreads();
        }
        float* cs = (float*)(sm + OFF_B);    // both B bufs free now
#pragma unroll
        for (int pass = 0; pass < 2; pass++) {
            combine_pass(cs, g_S1, 128, n0, pass, wm2, wn, g, tg, D0, D1);
            __syncthreads();
            scan_pass<false>(sm, cs, b1, 128, n0, pass, tid,
                             (uint16_t*)(sm + OFF_M1), nullptr, b0);
            __syncthreads();
        }
    }
    // ---- layer 1 repair (permuted M0, K=784, gmem W1) ----
    {
        int n = *(int*)(sm + OFF_FC);
        if (n > FCAPS) n = FCAPS;
        const uint64_t* m64 = (const uint64_t*)(sm + OFF_M0);
        for (int f0 = wid * 2; f0 < n; f0 += 16) {
            int s = f0 + (lane >> 4), tl = lane & 15;
            float acc = 0.0f;
            int bl = 0, j = 0;
            bool act = (s < n);
            if (act) {
                uint32_t pk = ((uint32_t*)(sm + OFF_FL))[s];
                bl = (int)(pk >> 16); j = (int)(pk & 0xFFFFu);
                const float* wr = W1 + (size_t)j * 784;
                const uint32_t bit = 1u << tl;
                for (int i = 0; i < 784; i++) {
                    uint64_t mv = m64[bl * 224 + (i >> 2)];
                    uint32_t half = (i & 1) ? (uint32_t)(mv >> 32) : (uint32_t)mv;
                    uint32_t mk = (half >> (((i >> 1) & 1) << 4)) & 0xFFFFu;
                    if (mk & bit) acc += wr[i];
                }
            }
            float bj = act ? __ldg(b1 + j) : 0.0f;
            uint32_t msk = repair_scan(acc, bj, lane);
            if (act && (lane & 15) == 0)
                ((uint16_t*)(sm + OFF_M1))[bl * 128 + j] = (uint16_t)msk;
        }
        __syncthreads();
        if (tid == 0) *(int*)(sm + OFF_FC) = 0;
        __syncthreads();
    }

    // ---- layers 2,3 + repairs (M3 aliases M1) ----
    layer_k128<2, 128, false>(sm, sbase, (const uint16_t*)(sm + OFF_M1),
                              g_Q2, g_S2, b2, (uint16_t*)(sm + OFF_M2),
                              nullptr, b0, tid, wm2, wn, g, tg);
    repair_k128<false>(sm, (const uint16_t*)(sm + OFF_M1), W2, b2,
                       (uint16_t*)(sm + OFF_M2), nullptr, 128, b0, tid, lane, wid);

    layer_k128<2, 128, false>(sm, sbase, (const uint16_t*)(sm + OFF_M2),
                              g_Q3, g_S3, b3, (uint16_t*)(sm + OFF_M1),
                              nullptr, b0, tid, wm2, wn, g, tg);
    repair_k128<false>(sm, (const uint16_t*)(sm + OFF_M2), W3, b3,
                       (uint16_t*)(sm + OFF_M1), nullptr, 128, b0, tid, lane, wid);

    // ---- layer 4 + repair ----
    layer_k128<13, 784, true>(sm, sbase, (const uint16_t*)(sm + OFF_M1),
                              g_Q4, g_S4, b4, nullptr, Out, b0,
                              tid, wm2, wn, g, tg);
    repair_k128<true>(sm, (const uint16_t*)(sm + OFF_M1), W4, b4,
                      nullptr, Out, 784, b0, tid, lane, wid);
}

// ---------------------------------------------------------------------------
extern "C" void kernel_launch(void* const* d_in, const int* in_sizes, int n_in,
                              void* d_out, int out_size)
{
    const float* features = (const float*)d_in[0];
    const float* W1 = (const float*)d_in[1];
    const float* b1 = (const float*)d_in[2];
    const float* W2 = (const float*)d_in[3];
    const float* b2 = (const float*)d_in[4];
    const float* W3 = (const float*)d_in[5];
    const float* b3 = (const float*)d_in[6];
    const float* W4 = (const float*)d_in[7];
    const float* b4 = (const float*)d_in[8];
    float* out = (float*)d_out;

    cudaFuncSetAttribute(fused_spike,
                         cudaFuncAttributeMaxDynamicSharedMemorySize, SMEMSZ);

    wsplit_all<<<1168, 32>>>(W1, W2, W3, W4);
    fused_spike<<<BATCH / 8, 256, SMEMSZ>>>(features, W1, b1, W2, b2,
                                            W3, b3, W4, b4, out);
}

// round 13
// speedup vs baseline: 1.0187x; 1.0144x over previous
#include <cuda_runtime.h>
#include <stdint.h>

// AE_spikes: ONE fused kernel, 8 batch rows/CTA, enc->L1->..->L4 in smem.
// s8 mma.sync, 2 weight limbs base 254, exact int32 accumulation, fused
// fire-and-reset scan, in-CTA flag + bit-exact fp32 repair.
// R12: A fragments built IN REGISTERS from permuted mask u64s (no A smem
// panel, no expansion barrier); freed 18KB -> full single-pass scan buffer;
// ~2x fewer __syncthreads; masks permuted end-to-end.

#define BATCH  16384
#define TSTEPS 16
#define KP1    896
#define EPS    1e-3f
#define FCAPS  512

// smem layout (bytes)
#define OFF_M0 0        // 8 x 896 u16 PERMUTED                (14336)
#define OFF_B0 14336    // B buf0                              (18432)
#define OFF_B1 32768    // B buf1 (L1 mainloop only)           (18432)
#define OFF_CS 32768    // scan buffer 128 x 68 f32            (34816) -> 67584
#define OFF_M1 67584    // 8 x 128 u16 PERMUTED                 (2048)
#define OFF_M2 69632    //                                      (2048)
#define OFF_FC 71680    // flag counter                           (16)
#define OFF_FL 71696    // flag list u32 x 512                  (2048)
#define SMEMSZ 73744

// logical neuron index -> permuted u16 slot (pairs (0,2),(1,3) per u64)
#define PERM4(i) (((i) & ~3) | ((((i) & 1) << 1) | (((i) >> 1) & 1)))

// ---------------- weight scratch ----------------
__device__ int8_t g_Q1[2 * 128 * KP1];
__device__ int8_t g_Q2[2 * 128 * 128];
__device__ int8_t g_Q3[2 * 128 * 128];
__device__ int8_t g_Q4[2 * 784 * 128];
__device__ float  g_S1[128], g_S2[128], g_S3[128], g_S4[784];

// ---------------- helpers ----------------
__device__ __forceinline__ uint32_t smem_u32(const void* p) {
    uint32_t a;
    asm("{ .reg .u64 t; cvta.to.shared.u64 t, %1; cvt.u32.u64 %0, t; }"
        : "=r"(a) : "l"(p));
    return a;
}
__device__ __forceinline__ void mma8(int* d, const uint32_t* a, uint32_t b0, uint32_t b1) {
    asm volatile(
        "mma.sync.aligned.m16n8k32.row.col.s32.s8.s8.s32 "
        "{%0,%1,%2,%3}, {%4,%5,%6,%7}, {%8,%9}, {%0,%1,%2,%3};"
        : "+r"(d[0]), "+r"(d[1]), "+r"(d[2]), "+r"(d[3])
        : "r"(a[0]), "r"(a[1]), "r"(a[2]), "r"(a[3]), "r"(b0), "r"(b1));
}
__device__ __forceinline__ void cpa16(uint32_t dst, const void* src, uint32_t ssz) {
    asm volatile("cp.async.cg.shared.global [%0], [%1], 16, %2;"
                 :: "r"(dst), "l"(src), "r"(ssz));
}

// ---------------- weight split (one launch) ----------------
__device__ void wsplit_one(const float* W, int8_t* Q, float* S,
                           int N, int K, int KP, int j, int lane) {
    const float* w = W + (size_t)j * K;
    float m = 0.0f;
    for (int k = lane; k < K; k += 32) m = fmaxf(m, fabsf(w[k]));
#pragma unroll
    for (int o = 16; o; o >>= 1) m = fmaxf(m, __shfl_xor_sync(~0u, m, o));
    float s0 = (m > 0.0f) ? m / 127.0f : 1.0f;
    if (lane == 0) S[j] = s0;
    double s0d = (double)s0;
    for (int k = lane; k < KP; k += 32) {
        double q0 = 0.0, q1 = 0.0;
        if (k < K) {
            double wd = (double)w[k];
            q0 = fmin(fmax(rint(wd / s0d), -127.0), 127.0);
            double r1 = wd - q0 * s0d;
            q1 = fmin(fmax(rint(r1 * 254.0 / s0d), -127.0), 127.0);
        }
        size_t base = (size_t)j * KP + k, lstr = (size_t)N * KP;
        Q[base]        = (int8_t)(int)q0;
        Q[base + lstr] = (int8_t)(int)q1;
    }
}
__global__ void __launch_bounds__(32) wsplit_all(
    const float* __restrict__ W1, const float* __restrict__ W2,
    const float* __restrict__ W3, const float* __restrict__ W4)
{
    int bid = blockIdx.x, lane = threadIdx.x;
    if      (bid < 128) wsplit_one(W1, g_Q1, g_S1, 128, 784, KP1, bid, lane);
    else if (bid < 256) wsplit_one(W2, g_Q2, g_S2, 128, 128, 128, bid - 128, lane);
    else if (bid < 384) wsplit_one(W3, g_Q3, g_S3, 128, 128, 128, bid - 256, lane);
    else                wsplit_one(W4, g_Q4, g_S4, 784, 128, 128, bid - 384, lane);
}

// ---------------- register A-expansion + MMA over one K=128 panel ---------
// Masks stored permuted per u64: lo=(m0|m2<<16), hi=(m1|m3<<16).
// A frag byte j of reg = bit t of m_j: a = ((lo>>t)&0x10001)|(((hi>>t)&0x10001)<<8).
__device__ __forceinline__ void mma_panel_reg(
    const char* sm, int msk_off, int kpu64, int p, const char* bbase,
    int wm2, int wn, int g, int tg,
    int (&D0)[2][4][4], int (&D1)[2][4][4])
{
    const uint64_t* m64 = (const uint64_t*)(sm + msk_off);
    const int p32 = p * 32;
#pragma unroll
    for (int ch = 0; ch < 4; ch++) {
        uint32_t afr[2][4];
#pragma unroll
        for (int mi = 0; mi < 2; mi++) {
            int base = (wm2 * 2 + mi) * kpu64 + p32 + ch * 8 + tg;
            uint64_t mv0 = m64[base];
            uint64_t mv1 = m64[base + 4];
            uint32_t lo0 = (uint32_t)mv0, hi0 = (uint32_t)(mv0 >> 32);
            uint32_t lo1 = (uint32_t)mv1, hi1 = (uint32_t)(mv1 >> 32);
            afr[mi][0] = ((lo0 >> g) & 0x00010001u) | (((hi0 >> g) & 0x00010001u) << 8);
            afr[mi][1] = ((lo0 >> (g + 8)) & 0x00010001u) | (((hi0 >> (g + 8)) & 0x00010001u) << 8);
            afr[mi][2] = ((lo1 >> g) & 0x00010001u) | (((hi1 >> g) & 0x00010001u) << 8);
            afr[mi][3] = ((lo1 >> (g + 8)) & 0x00010001u) | (((hi1 >> (g + 8)) & 0x00010001u) << 8);
        }
#pragma unroll
        for (int ni = 0; ni < 4; ni++) {
            const char* bb = bbase + (wn * 32 + ni * 8 + g) * 144 + ch * 32;
            uint32_t b00 = *(const uint32_t*)(bb + tg * 4);
            uint32_t b01 = *(const uint32_t*)(bb + 16 + tg * 4);
            mma8(D0[0][ni], afr[0], b00, b01);
            mma8(D0[1][ni], afr[1], b00, b01);
            uint32_t b10 = *(const uint32_t*)(bb + 9216 + tg * 4);
            uint32_t b11 = *(const uint32_t*)(bb + 9216 + 16 + tg * 4);
            mma8(D1[0][ni], afr[0], b10, b11);
            mma8(D1[1][ni], afr[1], b10, b11);
        }
    }
}

// combine (single pass, all warps): E = 254*D0 + D1, cs = (s0/254)*float(E)
__device__ __forceinline__ void combine_all(
    float* cs, const float* S, int NOUT, int n0,
    int wm2, int wn, int g, int tg,
    int (&D0)[2][4][4], int (&D1)[2][4][4])
{
#pragma unroll
    for (int mi = 0; mi < 2; mi++)
#pragma unroll
        for (int ni = 0; ni < 4; ni++)
#pragma unroll
            for (int rh = 0; rh < 2; rh++) {
                int row = wm2 * 32 + mi * 16 + g + rh * 8;
                int col = wn * 32 + ni * 8 + tg * 2;
                int jg0 = n0 + col;
                float sc0 = __ldg(S + (jg0 < NOUT ? jg0 : 0)) * (1.0f / 254.0f);
                float sc1 = __ldg(S + (jg0 + 1 < NOUT ? jg0 + 1 : 0)) * (1.0f / 254.0f);
                int E0 = D0[mi][ni][rh * 2] * 254 + D1[mi][ni][rh * 2];
                int E1 = D0[mi][ni][rh * 2 + 1] * 254 + D1[mi][ni][rh * 2 + 1];
                *(float2*)(cs + row * 68 + col) =
                    make_float2(sc0 * (float)E0, sc1 * (float)E1);
            }
}

// scan: 512 (bl,j) chains, 2 per thread; flags near-threshold pairs
template <bool IS_LAST>
__device__ __forceinline__ void scan_all(
    char* sm, const float* cs, const float* bias, int NOUT, int n0,
    int tid, int msk_out_off, float* Out, int b0)
{
#pragma unroll
    for (int u = 0; u < 2; u++) {
        int pr = tid + 256 * u;
        int j = pr & 63, bl = pr >> 6;
        int jj = n0 + j;
        if (jj < NOUT) {
            float bj = __ldg(bias + jj);
            const float* colp = cs + bl * 16 * 68 + j;
            float v = 0.0f;
            uint32_t msk = 0;
            bool flag = false;
#pragma unroll
            for (int t = 0; t < 16; t++) {
                v = (v + colp[t * 68]) + bj;
                flag |= (fabsf(v - 1.0f) < EPS);
                if (v >= 1.0f) { msk |= (1u << t); v -= 1.0f; }
            }
            if (IS_LAST)
                Out[(size_t)(b0 + bl) * NOUT + jj] = (float)__popc(msk) * 0.0625f;
            else
                ((uint16_t*)(sm + msk_out_off))[bl * 128 + PERM4(jj)] = (uint16_t)msk;
            if (flag) {
                int s = atomicAdd((int*)(sm + OFF_FC), 1);
                if (s < FCAPS) ((uint32_t*)(sm + OFF_FL))[s] =
                    ((uint32_t)bl << 16) | (uint32_t)jj;
            }
        }
    }
}

__device__ __forceinline__ uint32_t repair_scan(float acc, float bj, int lane) {
    float v = 0.0f;
    uint32_t msk = 0;
#pragma unroll
    for (int t = 0; t < TSTEPS; t++) {
        float a = __shfl_sync(0xFFFFFFFFu, acc, (lane & 16) + t);
        v = (v + a) + bj;
        if (v >= 1.0f) { msk |= (1u << t); v -= 1.0f; }
    }
    return msk;
}

// ---------------- K=128 layer: NT tiles, single-pass epilogue -------------
template <int NT, int NOUT, bool IS_LAST>
__device__ void layer_k128(char* sm, uint32_t sbase, int msk_in_off,
                           const int8_t* Q, const float* S, const float* bias,
                           int msk_out_off, float* Out, int b0,
                           int tid, int wm2, int wn, int g, int tg)
{
    auto loadB = [&](int nt) {
        const int n0 = nt * 64;
        for (int v = tid; v < 1024; v += 256) {
            int l = v >> 9, rem = v & 511, r = rem >> 3, c8 = rem & 7;
            int row = n0 + r;
            uint32_t ssz = (row < NOUT) ? 16u : 0u;
            int rc = row < NOUT ? row : 0;
            cpa16(sbase + OFF_B0 + l * 9216 + r * 144 + c8 * 16,
                  Q + ((size_t)l * NOUT + rc) * 128 + c8 * 16, ssz);
        }
        asm volatile("cp.async.commit_group;");
    };
    loadB(0);
    asm volatile("cp.async.wait_group 0;");
    __syncthreads();

#pragma unroll 1
    for (int nt = 0; nt < NT; nt++) {
        const int n0 = nt * 64;
        int D0[2][4][4], D1[2][4][4];
#pragma unroll
        for (int mi = 0; mi < 2; mi++)
#pragma unroll
            for (int ni = 0; ni < 4; ni++)
#pragma unroll
                for (int r = 0; r < 4; r++) { D0[mi][ni][r] = 0; D1[mi][ni][r] = 0; }

        mma_panel_reg(sm, msk_in_off, 32, 0, sm + OFF_B0, wm2, wn, g, tg, D0, D1);
        combine_all((float*)(sm + OFF_CS), S, NOUT, n0, wm2, wn, g, tg, D0, D1);
        __syncthreads();                 // mma+combine done: B0 reusable, cs readable
        if (nt + 1 < NT) loadB(nt + 1);  // overlaps scan
        scan_all<IS_LAST>(sm, (const float*)(sm + OFF_CS), bias, NOUT, n0,
                          tid, msk_out_off, Out, b0);
        if (nt + 1 < NT) asm volatile("cp.async.wait_group 0;");
        __syncthreads();                 // scan done + next B ready
    }
}

// ---------------- K=128 repair (masks permuted; ascending-i order) --------
template <bool IS_LAST>
__device__ void repair_k128(char* sm, int msk_prev_off, const float* W,
                            const float* bias, int msk_fix_off, float* Out,
                            int NOUT, int b0, int tid, int lane, int wid)
{
    int n = *(int*)(sm + OFF_FC);
    if (n > FCAPS) n = FCAPS;
    const uint16_t* mp = (const uint16_t*)(sm + msk_prev_off);
    for (int f0 = wid * 2; f0 < n; f0 += 16) {
        int s = f0 + (lane >> 4), tl = lane & 15;
        float acc = 0.0f;
        int bl = 0, j = 0;
        bool act = (s < n);
        if (act) {
            uint32_t pk = ((uint32_t*)(sm + OFF_FL))[s];
            bl = (int)(pk >> 16); j = (int)(pk & 0xFFFFu);
            const float* wr = W + (size_t)j * 128;
            const uint32_t bit = 1u << tl;
            const uint16_t* mr = mp + bl * 128;
            for (int i4 = 0; i4 < 128; i4 += 4) {   // logical ascending order
                if (mr[i4 + 0] & bit) acc += wr[i4 + 0];
                if (mr[i4 + 2] & bit) acc += wr[i4 + 1];
                if (mr[i4 + 1] & bit) acc += wr[i4 + 2];
                if (mr[i4 + 3] & bit) acc += wr[i4 + 3];
            }
        }
        float bj = act ? __ldg(bias + j) : 0.0f;
        uint32_t msk = repair_scan(acc, bj, lane);
        if (act && (lane & 15) == 0) {
            if (IS_LAST)
                Out[(size_t)(b0 + bl) * NOUT + j] = (float)__popc(msk) * 0.0625f;
            else
                ((uint16_t*)(sm + msk_fix_off))[bl * 128 + PERM4(j)] = (uint16_t)msk;
        }
    }
    __syncthreads();
    if (tid == 0) *(int*)(sm + OFF_FC) = 0;
    __syncthreads();
}

// ---------------- the fused kernel ----------------
__global__ void __launch_bounds__(256, 3) fused_spike(
    const float* __restrict__ F,
    const float* __restrict__ W1, const float* __restrict__ b1,
    const float* __restrict__ W2, const float* __restrict__ b2,
    const float* __restrict__ W3, const float* __restrict__ b3,
    const float* __restrict__ W4, const float* __restrict__ b4,
    float* __restrict__ Out)
{
    extern __shared__ __align__(16) char sm[];
    const uint32_t sbase = smem_u32(sm);
    const int tid = threadIdx.x;
    const int lane = tid & 31, wid = tid >> 5;
    const int wm2 = wid >> 1, wn = wid & 1;
    const int g = lane >> 2, tg = lane & 3;
    const int b0 = blockIdx.x * 8;

    // ---- encoder (bit-exact), written directly permuted ----
    {
        uint16_t* m0 = (uint16_t*)(sm + OFF_M0);
#pragma unroll 1
        for (int bl = 0; bl < 8; bl++) {
            const float* fr = F + (size_t)(b0 + bl) * 784;
            for (int i = tid; i < KP1; i += 256) {
                unsigned m = 0;
                if (i < 784) {
                    float x = fr[i], v = 0.0f;
#pragma unroll
                    for (int t = 0; t < TSTEPS; t++) {
                        v += x;
                        if (v >= 1.0f) { m |= (1u << t); v -= 1.0f; }
                    }
                }
                m0[bl * KP1 + PERM4(i)] = (uint16_t)m;
            }
        }
        if (tid == 0) *(int*)(sm + OFF_FC) = 0;
        __syncthreads();
    }

    // ---- layer 1: K=896, 2 N-tiles, double-buffered panels ----
#pragma unroll 1
    for (int nt = 0; nt < 2; nt++) {
        const int n0 = nt * 64;
        int D0[2][4][4], D1[2][4][4];
#pragma unroll
        for (int mi = 0; mi < 2; mi++)
#pragma unroll
            for (int ni = 0; ni < 4; ni++)
#pragma unroll
                for (int r = 0; r < 4; r++) { D0[mi][ni][r] = 0; D1[mi][ni][r] = 0; }

        auto loadB1 = [&](int p, int buf) {
            for (int v = tid; v < 1024; v += 256) {
                int l = v >> 9, rem = v & 511, r = rem >> 3, c8 = rem & 7;
                cpa16(sbase + OFF_B0 + buf * 18432 + l * 9216 + r * 144 + c8 * 16,
                      g_Q1 + ((size_t)l * 128 + n0 + r) * KP1 + p * 128 + c8 * 16, 16u);
            }
            asm volatile("cp.async.commit_group;");
        };
        loadB1(0, 0);
        asm volatile("cp.async.wait_group 0;");
        __syncthreads();
#pragma unroll 1
        for (int p = 0; p < 7; p++) {
            const int buf = p & 1;
            if (p < 6) loadB1(p + 1, buf ^ 1);   // buf^1 free (synced last iter)
            mma_panel_reg(sm, OFF_M0, KP1 / 4, p, sm + OFF_B0 + buf * 18432,
                          wm2, wn, g, tg, D0, D1);
            if (p < 6) asm volatile("cp.async.wait_group 0;");
            __syncthreads();                     // mma(buf) done + B(p+1) ready
        }
        combine_all((float*)(sm + OFF_CS), g_S1, 128, n0, wm2, wn, g, tg, D0, D1);
        __syncthreads();
        scan_all<false>(sm, (const float*)(sm + OFF_CS), b1, 128, n0,
                        tid, OFF_M1, nullptr, b0);
        __syncthreads();
    }
    // ---- layer 1 repair (permuted M0, K=784, gmem W1) ----
    {
        int n = *(int*)(sm + OFF_FC);
        if (n > FCAPS) n = FCAPS;
        const uint16_t* mp = (const uint16_t*)(sm + OFF_M0);
        for (int f0 = wid * 2; f0 < n; f0 += 16) {
            int s = f0 + (lane >> 4), tl = lane & 15;
            float acc = 0.0f;
            int bl = 0, j = 0;
            bool act = (s < n);
            if (act) {
                uint32_t pk = ((uint32_t*)(sm + OFF_FL))[s];
                bl = (int)(pk >> 16); j = (int)(pk & 0xFFFFu);
                const float* wr = W1 + (size_t)j * 784;
                const uint32_t bit = 1u << tl;
                const uint16_t* mr = mp + bl * KP1;
                for (int i4 = 0; i4 < 784; i4 += 4) {
                    if (mr[i4 + 0] & bit) acc += wr[i4 + 0];
                    if (mr[i4 + 2] & bit) acc += wr[i4 + 1];
                    if (mr[i4 + 1] & bit) acc += wr[i4 + 2];
                    if (mr[i4 + 3] & bit) acc += wr[i4 + 3];
                }
            }
            float bj = act ? __ldg(b1 + j) : 0.0f;
            uint32_t msk = repair_scan(acc, bj, lane);
            if (act && (lane & 15) == 0)
                ((uint16_t*)(sm + OFF_M1))[bl * 128 + PERM4(j)] = (uint16_t)msk;
        }
        __syncthreads();
        if (tid == 0) *(int*)(sm + OFF_FC) = 0;
        __syncthreads();
    }

    // ---- layers 2,3 + repairs (M3 aliases M1) ----
    layer_k128<2, 128, false>(sm, sbase, OFF_M1, g_Q2, g_S2, b2,
                              OFF_M2, nullptr, b0, tid, wm2, wn, g, tg);
    repair_k128<false>(sm, OFF_M1, W2, b2, OFF_M2, nullptr, 128,
                       b0, tid, lane, wid);

    layer_k128<2, 128, false>(sm, sbase, OFF_M2, g_Q3, g_S3, b3,
                              OFF_M1, nullptr, b0, tid, wm2, wn, g, tg);
    repair_k128<false>(sm, OFF_M2, W3, b3, OFF_M1, nullptr, 128,
                       b0, tid, lane, wid);

    // ---- layer 4 + repair ----
    layer_k128<13, 784, true>(sm, sbase, OFF_M1, g_Q4, g_S4, b4,
                              0, Out, b0, tid, wm2, wn, g, tg);
    repair_k128<true>(sm, OFF_M1, W4, b4, 0, Out, 784, b0, tid, lane, wid);
}

// ---------------------------------------------------------------------------
extern "C" void kernel_launch(void* const* d_in, const int* in_sizes, int n_in,
                              void* d_out, int out_size)
{
    const float* features = (const float*)d_in[0];
    const float* W1 = (const float*)d_in[1];
    const float* b1 = (const float*)d_in[2];
    const float* W2 = (const float*)d_in[3];
    const float* b2 = (const float*)d_in[4];
    const float* W3 = (const float*)d_in[5];
    const float* b3 = (const float*)d_in[6];
    const float* W4 = (const float*)d_in[7];
    const float* b4 = (const float*)d_in[8];
    float* out = (float*)d_out;

    cudaFuncSetAttribute(fused_spike,
                         cudaFuncAttributeMaxDynamicSharedMemorySize, SMEMSZ);

    wsplit_all<<<1168, 32>>>(W1, W2, W3, W4);
    fused_spike<<<BATCH / 8, 256, SMEMSZ>>>(features, W1, b1, W2, b2,
                                            W3, b3, W4, b4, out);
}